// round 12
// baseline (speedup 1.0000x reference)
#include <cuda_runtime.h>
#include <math.h>

#define BB   16
#define NN   1024
#define HID  32
#define K1   205
#define K2   41
#define K1PAD 208
#define MAXD 96
#define OUTD 4
#define FULL 0xffffffffu
#define SLABS 26
#define ROWS_PER_SLAB 8
#define UPSLABS 8
#define UPROWS 26

// ---------------- scratch (device globals; no allocation) ----------------
__device__ float    g_dis0[BB*NN];
__device__ int      g_cnt[BB*NN];
__device__ int      g_csr[BB*NN*MAXD];
__device__ float    g_z0[BB*NN*HID];
__device__ float    g_h0[BB*NN*HID];
__device__ float    g_score1[BB*NN];
__device__ int      g_perm1[BB*K1];
__device__ float    g_vals1[BB*K1];
__device__ int      g_inv1[BB*NN];
__device__ unsigned g_bmT[BB*32*K1PAD];     // transposed: [b][word][k]
__device__ float    g_A1[BB*K1*K1];
__device__ float    g_dis1[BB*K1];
__device__ float    g_z1[BB*K1*HID];
__device__ float    g_h1[BB*K1*HID];
__device__ float    g_score2[BB*K1];
__device__ int      g_perm2[BB*K2];
__device__ float    g_vals2[BB*K2];
__device__ int      g_inv2[BB*K1];
__device__ float    g_A2[BB*K2*K2];
__device__ float    g_dis2[BB*K2];
__device__ float    g_z2[BB*K2*HID];
__device__ float    g_hu[BB*K1*HID];
__device__ float    g_zu1[BB*NN*HID];
__device__ float    g_hf[BB*NN*HID];
__device__ float    g_part[64*HID];
__device__ float    g_part2[64*HID];

// ---------------- bitonic sort: desc key, asc index on tie ----------------
template<int SIZE, int NT>
__device__ __forceinline__ void bitonic(float* key, int* idx, int t){
  for (int k = 2; k <= SIZE; k <<= 1){
    for (int j = k >> 1; j > 0; j >>= 1){
      __syncthreads();
      for (int i = t; i < SIZE; i += NT){
        int ixj = i ^ j;
        if (ixj > i){
          float ka = key[i], kb = key[ixj];
          int   ia = idx[i], ib = idx[ixj];
          bool aFirst = (ka > kb) || (ka == kb && ia < ib);
          bool up = ((i & k) == 0);
          if (up ? !aFirst : aFirst){
            key[i] = kb; key[ixj] = ka;
            idx[i] = ib; idx[ixj] = ia;
          }
        }
      }
    }
  }
  __syncthreads();
}

// ---------------- K1: CSR build (warp-ballot scan) + dis0 + z0 -------------
__global__ void k_csr(const float* __restrict__ adj, const float* __restrict__ x,
                      const float* __restrict__ Wd0){
  int row = blockIdx.x;               // b*NN + i
  int t   = threadIdx.x;              // 256 threads, 4 cols each (float4)
  int w   = t >> 5, lane = t & 31;
  const float4* arow = (const float4*)(adj + (size_t)row * NN);
  float4 v = arow[t];
  int c0 = v.x != 0.f, c1 = v.y != 0.f, c2 = v.z != 0.f, c3 = v.w != 0.f;
  unsigned m0 = __ballot_sync(FULL, c0);
  unsigned m1 = __ballot_sync(FULL, c1);
  unsigned m2 = __ballot_sync(FULL, c2);
  unsigned m3 = __ballot_sync(FULL, c3);
  int wtotal = __popc(m0) + __popc(m1) + __popc(m2) + __popc(m3);
  __shared__ int swt[8];
  if (lane == 0) swt[w] = wtotal;
  __syncthreads();
  int wbase = 0, total = 0;
  #pragma unroll
  for (int q = 0; q < 8; q++){
    int tv = swt[q];
    if (q < w) wbase += tv;
    total += tv;
  }
  unsigned lt = (1u << lane) - 1u;
  int p0 = wbase + __popc(m0 & lt);
  int p1 = wbase + __popc(m0) + __popc(m1 & lt);
  int p2 = wbase + __popc(m0) + __popc(m1) + __popc(m2 & lt);
  int p3 = wbase + __popc(m0) + __popc(m1) + __popc(m2) + __popc(m3 & lt);
  int* crow = g_csr + (size_t)row * MAXD;
  int jb = t * 4;
  if (c0 && p0 < MAXD) crow[p0] = jb;
  if (c1 && p1 < MAXD) crow[p1] = jb + 1;
  if (c2 && p2 < MAXD) crow[p2] = jb + 2;
  if (c3 && p3 < MAXD) crow[p3] = jb + 3;
  float dis = rsqrtf((float)total + 2.f);      // deg = rowsum + 2, always > 0
  if (t == 0){ g_cnt[row] = total < MAXD ? total : MAXD; g_dis0[row] = dis; }
  if (t < HID){
    const float* xr = x + (size_t)row * 3;
    float z = xr[0]*Wd0[t] + xr[1]*Wd0[HID + t] + xr[2]*Wd0[2*HID + t];
    g_z0[row*HID + t] = dis * z;
  }
}

// ---------------- K2: gcn0 aggregate + relu + score1 ----------------------
__global__ void k_gcn0(const float* __restrict__ bd0, const float* __restrict__ p1){
  int w = (blockIdx.x * blockDim.x + threadIdx.x) >> 5;
  int lane = threadIdx.x & 31;
  if (w >= BB*NN) return;
  int b = w >> 10;
  const float* zb = g_z0 + (size_t)b * NN * HID;
  float a0 = 2.f * g_z0[(size_t)w * HID + lane], a1 = 0.f;
  int cnt = g_cnt[w];
  const int* crow = g_csr + (size_t)w * MAXD;
  int q = 0;
  for (; q + 1 < cnt; q += 2){
    a0 += zb[crow[q]*HID + lane];
    a1 += zb[crow[q+1]*HID + lane];
  }
  if (q < cnt) a0 += zb[crow[q]*HID + lane];
  float h = fmaxf(g_dis0[w]*(a0+a1) + bd0[lane], 0.f);
  g_h0[(size_t)w*HID + lane] = h;
  float pv = p1[lane];
  float s = h * pv, pn = pv * pv;
  #pragma unroll
  for (int o = 16; o > 0; o >>= 1){
    s  += __shfl_xor_sync(FULL, s,  o);
    pn += __shfl_xor_sync(FULL, pn, o);
  }
  if (lane == 0) g_score1[w] = tanhf(s * rsqrtf(pn));
}

// ---------------- K3: top-k level1 + inverse map + transposed bitmaps -----
__global__ void k_top1(){
  int b = blockIdx.x;
  int t = threadIdx.x;                // 512 threads
  __shared__ float skey[NN];
  __shared__ int   sidx[NN];
  for (int i = t; i < NN; i += 512){ skey[i] = g_score1[b*NN + i]; sidx[i] = i; }
  bitonic<NN,512>(skey, sidx, t);
  for (int i = t; i < NN; i += 512) g_inv1[b*NN + i] = -1;
  __syncthreads();
  if (t < K1){
    g_perm1[b*K1 + t] = sidx[t];
    g_vals1[b*K1 + t] = skey[t];
    g_inv1[b*NN + sidx[t]] = t;
  }
  unsigned* bmb = g_bmT + (size_t)b * 32 * K1PAD;
  for (int q = t; q < 32*K1PAD; q += 512) bmb[q] = 0u;
  __syncthreads();
  int wq = t >> 5, lane = t & 31;
  for (int k = wq; k < K1; k += 16){
    int r = sidx[k];
    int rw = b*NN + r;
    int cnt = g_cnt[rw];
    const int* crow = g_csr + (size_t)rw * MAXD;
    for (int q = lane; q < cnt; q += 32){
      int nb = crow[q];
      atomicOr(&bmb[(nb >> 5)*K1PAD + k], 1u << (nb & 31));
    }
    if (lane == 0) atomicOr(&bmb[(r >> 5)*K1PAD + k], 1u << (r & 31));  // +I
  }
}

// ---------------- K4: A1 = augment(adj)[perm1,perm1] + dis1 + z1 ----------
__global__ void k_A1(const float* __restrict__ Wd1){
  int b    = blockIdx.x / SLABS;
  int slab = blockIdx.x % SLABS;
  int t = threadIdx.x;                // 256 threads = 8 warps
  int w = t >> 5, lane = t & 31;
  __shared__ unsigned s_bmT[32*K1PAD];
  const unsigned* bmb = g_bmT + (size_t)b * 32 * K1PAD;
  for (int q = t; q < 32*K1PAD; q += 256) s_bmT[q] = bmb[q];
  __syncthreads();

  int i = slab * ROWS_PER_SLAB + w;
  if (i >= K1) return;
  unsigned bi[32];
  #pragma unroll
  for (int wd = 0; wd < 32; wd++) bi[wd] = s_bmT[wd*K1PAD + i];
  int rowsum = 0;
  float* Arow = g_A1 + (size_t)(b*K1 + i) * K1;
  for (int jb = 0; jb < K1; jb += 32){
    int j = jb + lane;
    int jj = (j < K1) ? j : 0;        // clamp padded lanes (result discarded)
    int c0 = 0, c1 = 0;               // 2 chains: halve dependent-IADD latency
    #pragma unroll
    for (int wd = 0; wd < 16; wd++)
      c0 += __popc(bi[wd] & s_bmT[wd*K1PAD + jj]);
    #pragma unroll
    for (int wd = 16; wd < 32; wd++)
      c1 += __popc(bi[wd] & s_bmT[wd*K1PAD + jj]);
    if (j < K1){
      int v = (j == i) ? 0 : (c0 + c1);
      Arow[j] = (float)v;
      rowsum += v;
    }
  }
  #pragma unroll
  for (int o = 16; o > 0; o >>= 1) rowsum += __shfl_xor_sync(FULL, rowsum, o);
  float dis = rsqrtf((float)rowsum + 2.f);
  if (lane == 0) g_dis1[b*K1 + i] = dis;
  int src = g_perm1[b*K1 + i];
  float val = g_vals1[b*K1 + i];
  const float* h0r = g_h0 + (size_t)(b*NN + src) * HID;
  float acc = 0.f;
  #pragma unroll
  for (int g = 0; g < HID; g++) acc += h0r[g]*val * Wd1[g*HID + lane];
  g_z1[(size_t)(b*K1 + i)*HID + lane] = dis * acc;
}

// ---------------- K5: gcn1 aggregate + relu + score2 ----------------------
__global__ void k_gcn1(const float* __restrict__ bd1, const float* __restrict__ p2){
  int w = (blockIdx.x * blockDim.x + threadIdx.x) >> 5;
  int lane = threadIdx.x & 31;
  if (w >= BB*K1) return;
  int b = w / K1, i = w - b*K1;
  const float* z  = g_z1 + (size_t)b * K1 * HID;
  const float* Ar = g_A1 + (size_t)w * K1;
  float a0 = 2.f * z[i*HID + lane], a1 = 0.f, a2 = 0.f, a3 = 0.f;
  int j = 0;
  for (; j + 3 < K1; j += 4){
    a0 += Ar[j]   * z[j*HID     + lane];
    a1 += Ar[j+1] * z[(j+1)*HID + lane];
    a2 += Ar[j+2] * z[(j+2)*HID + lane];
    a3 += Ar[j+3] * z[(j+3)*HID + lane];
  }
  for (; j < K1; j++) a0 += Ar[j] * z[j*HID + lane];
  float h = fmaxf(g_dis1[w]*((a0+a1)+(a2+a3)) + bd1[lane], 0.f);
  g_h1[(size_t)w*HID + lane] = h;
  float pv = p2[lane];
  float s = h * pv, pn = pv * pv;
  #pragma unroll
  for (int o = 16; o > 0; o >>= 1){
    s  += __shfl_xor_sync(FULL, s,  o);
    pn += __shfl_xor_sync(FULL, pn, o);
  }
  if (lane == 0) g_score2[w] = tanhf(s * rsqrtf(pn));
}

// ---------------- K6: top-k level2 + inverse map ---------------------------
__global__ void k_top2(){
  int b = blockIdx.x, t = threadIdx.x;   // 128 threads
  __shared__ float skey[256];
  __shared__ int   sidx[256];
  for (int i = t; i < 256; i += 128){
    skey[i] = (i < K1) ? g_score2[b*K1 + i] : -2.f;   // scores in [-1,1]
    sidx[i] = i;
  }
  bitonic<256,128>(skey, sidx, t);
  for (int i = t; i < K1; i += 128) g_inv2[b*K1 + i] = -1;
  __syncthreads();
  if (t < K2){
    g_perm2[b*K2 + t] = sidx[t];
    g_vals2[b*K2 + t] = skey[t];
    g_inv2[b*K1 + sidx[t]] = t;
  }
}

// ---------------- K7: A2 = augment(A1)[perm2,perm2] + dis2 + z2 -----------
__global__ void k_lvl2(const float* __restrict__ Wd2){
  int b = blockIdx.x / K2, i = blockIdx.x % K2;
  __shared__ float srow[K1];
  __shared__ float ssum;
  int t = threadIdx.x;                 // 256 threads
  int pi = g_perm2[b*K2 + i];
  if (t == 0) ssum = 0.f;
  for (int q = t; q < K1; q += 256)
    srow[q] = g_A1[(size_t)(b*K1 + pi)*K1 + q] + (q == pi ? 1.f : 0.f);
  __syncthreads();
  float local = 0.f;
  if (t < K2){
    int pj = g_perm2[b*K2 + t];
    const float* Aj = g_A1 + (size_t)(b*K1 + pj)*K1;
    float dot = 0.f;
    for (int q = 0; q < K1; q++) dot += srow[q] * (Aj[q] + (q == pj ? 1.f : 0.f));
    float v = (t == i) ? 0.f : dot;
    g_A2[(size_t)(b*K2 + i)*K2 + t] = v;
    local = v;
  }
  atomicAdd(&ssum, local);             // exact integer sums
  __syncthreads();
  float dis = rsqrtf(ssum + 2.f);
  if (t == 0) g_dis2[b*K2 + i] = dis;
  if (t < HID){
    int src = g_perm2[b*K2 + i];
    float val = g_vals2[b*K2 + i];
    const float* h1r = g_h1 + (size_t)(b*K1 + src) * HID;
    float acc = 0.f;
    #pragma unroll
    for (int g = 0; g < HID; g++) acc += h1r[g]*val * Wd2[g*HID + t];
    g_z2[(size_t)(b*K2 + i)*HID + t] = dis * acc;
  }
}

// ---------------- K8: fused gcn2 + zu0 + gcnu0 -> g_hu ---------------------
// grid = BB * UPSLABS (128 blocks); h2/zu0 recomputed redundantly per slab.
__global__ void k_up(const float* __restrict__ bd2, const float* __restrict__ Wu0,
                     const float* __restrict__ bu0){
  __shared__ float s_z2[K2*HID];      // 5.2 KB
  __shared__ float s_h2[K2*HID];      // 5.2 KB
  __shared__ float s_W[HID*HID];      // 4 KB
  __shared__ float s_zu0[K1*HID];     // 26.2 KB
  __shared__ float s_dis1[K1];
  int b = blockIdx.x >> 3, slab = blockIdx.x & 7;
  int t = threadIdx.x, w = t >> 5, lane = t & 31;
  for (int q = t; q < K2*HID; q += 256) s_z2[q] = g_z2[b*K2*HID + q];
  for (int q = t; q < HID*HID; q += 256) s_W[q] = Wu0[q];
  for (int q = t; q < K1; q += 256) s_dis1[q] = g_dis1[b*K1 + q];
  __syncthreads();
  // h2 = relu(dis2 * (2*z2 + A2 @ z2) + bd2)
  for (int q = t; q < K2*HID; q += 256){
    int i = q >> 5, f = q & 31;
    const float* Ar = g_A2 + (size_t)(b*K2 + i)*K2;
    float acc = 2.f * s_z2[q];
    for (int j = 0; j < K2; j++) acc += Ar[j] * s_z2[j*HID + f];
    s_h2[q] = fmaxf(g_dis2[b*K2 + i]*acc + bd2[f], 0.f);
  }
  __syncthreads();
  // zu0 = dis1 * ((h1 + scatter(h2)) @ Wu0)  for ALL K1 rows
  for (int q = t; q < K1*HID; q += 256){
    int k = q >> 5, f = q & 31;
    int iv = g_inv2[b*K1 + k];
    const float* h1r = g_h1 + (size_t)(b*K1 + k)*HID;
    float acc = 0.f;
    if (iv >= 0){
      const float* h2r = s_h2 + iv*HID;
      #pragma unroll
      for (int g = 0; g < HID; g++) acc += (h1r[g] + h2r[g]) * s_W[g*HID + f];
    } else {
      #pragma unroll
      for (int g = 0; g < HID; g++) acc += h1r[g] * s_W[g*HID + f];
    }
    s_zu0[q] = s_dis1[k] * acc;
  }
  __syncthreads();
  // gcnu0 for this slab's rows
  int iend = slab*UPROWS + UPROWS; if (iend > K1) iend = K1;
  for (int i = slab*UPROWS + w; i < iend; i += 8){
    const float* Ar = g_A1 + (size_t)(b*K1 + i)*K1;
    float a0 = 2.f * s_zu0[i*HID + lane], a1 = 0.f, a2 = 0.f, a3 = 0.f;
    int j = 0;
    for (; j + 3 < K1; j += 4){
      a0 += Ar[j]   * s_zu0[j*HID     + lane];
      a1 += Ar[j+1] * s_zu0[(j+1)*HID + lane];
      a2 += Ar[j+2] * s_zu0[(j+2)*HID + lane];
      a3 += Ar[j+3] * s_zu0[(j+3)*HID + lane];
    }
    for (; j < K1; j++) a0 += Ar[j] * s_zu0[j*HID + lane];
    g_hu[(size_t)(b*K1 + i)*HID + lane] =
        fmaxf(s_dis1[i]*((a0+a1)+(a2+a3)) + bu0[lane], 0.f);
  }
}

// ---------------- K9: zu1 = dis0 * ((h0 + scatter(hu)) @ Wu1) -------------
__global__ void k_zu1(const float* __restrict__ Wu1){
  int idx = blockIdx.x * blockDim.x + threadIdx.x;   // < BB*NN*HID
  int f = idx & 31;
  int rn = idx >> 5;                   // b*NN + n
  int b = rn >> 10;
  int iv = g_inv1[rn];
  const float* h0r = g_h0 + (size_t)rn * HID;
  const float* hur = g_hu + (size_t)(b*K1 + (iv < 0 ? 0 : iv)) * HID;
  float acc = 0.f;
  #pragma unroll
  for (int g = 0; g < HID; g++){
    float us = h0r[g] + (iv >= 0 ? hur[g] : 0.f);
    acc += us * Wu1[g*HID + f];
  }
  g_zu1[idx] = g_dis0[rn] * acc;
}

// ---------------- K10: final gcn via CSR (no relu) -> hf -------------------
__global__ void k_gcnf(const float* __restrict__ bu1){
  int w = (blockIdx.x * blockDim.x + threadIdx.x) >> 5;
  int lane = threadIdx.x & 31;
  if (w >= BB*NN) return;
  int b = w >> 10;
  const float* zb = g_zu1 + (size_t)b * NN * HID;
  float a0 = 2.f * g_zu1[(size_t)w*HID + lane], a1 = 0.f;
  int cnt = g_cnt[w];
  const int* crow = g_csr + (size_t)w * MAXD;
  int q = 0;
  for (; q + 1 < cnt; q += 2){
    a0 += zb[crow[q]*HID + lane];
    a1 += zb[crow[q+1]*HID + lane];
  }
  if (q < cnt) a0 += zb[crow[q]*HID + lane];
  g_hf[(size_t)w*HID + lane] = g_dis0[w]*(a0+a1) + bu1[lane];
}

// ---------------- K11: batch-norm stats stage 1 ----------------------------
__global__ void k_bn1(){
  int blk = blockIdx.x;                // 64 blocks
  int t = threadIdx.x;
  int w = t >> 5, lane = t & 31;
  float s = 0.f, s2 = 0.f;
  int rowbase = blk * 256;
  for (int r = w; r < 256; r += 8){
    float v = g_hf[(size_t)(rowbase + r)*HID + lane];
    s += v; s2 += v*v;
  }
  __shared__ float sh[8][32], sh2[8][32];
  sh[w][lane] = s; sh2[w][lane] = s2;
  __syncthreads();
  if (w == 0){
    float a = 0.f, a2 = 0.f;
    #pragma unroll
    for (int q = 0; q < 8; q++){ a += sh[q][lane]; a2 += sh2[q][lane]; }
    g_part[blk*HID + lane]  = a;
    g_part2[blk*HID + lane] = a2;
  }
}

// ---------------- K12: fused BN-finalize + BN-apply + MLP + sigmoid --------
__global__ void k_mlp(const float* __restrict__ gamma, const float* __restrict__ beta,
                      const float* __restrict__ W1, const float* __restrict__ b1,
                      const float* __restrict__ W2, const float* __restrict__ b2,
                      const float* __restrict__ W3, const float* __restrict__ b3,
                      float* __restrict__ out){
  int t = threadIdx.x;                // 256 threads = 8 warps
  int w = t >> 5, lane = t & 31;
  __shared__ float sp[8][32], sp2[8][32];
  __shared__ float s_scale[32], s_shift[32];
  __shared__ float sW1[HID*HID], sW2[HID*HID], sW3[HID*OUTD];
  // stage weights
  for (int q = t; q < HID*HID; q += 256){ sW1[q] = W1[q]; sW2[q] = W2[q]; }
  if (t < HID*OUTD) sW3[t] = W3[t];
  // redundant per-block BN finalize (deterministic fixed-order sums)
  float ps = 0.f, ps2 = 0.f;
  for (int q = w*8; q < w*8 + 8; q++){
    ps  += g_part[q*HID + lane];
    ps2 += g_part2[q*HID + lane];
  }
  sp[w][lane] = ps; sp2[w][lane] = ps2;
  __syncthreads();
  if (w == 0){
    float s = 0.f, s2 = 0.f;
    #pragma unroll
    for (int q = 0; q < 8; q++){ s += sp[q][lane]; s2 += sp2[q][lane]; }
    const float inv = 1.f / (float)(BB*NN);
    float mean = s * inv;
    float var  = s2 * inv - mean*mean;
    float sc = gamma[lane] * rsqrtf(var + 1e-5f);
    s_scale[lane] = sc;
    s_shift[lane] = beta[lane] - mean*sc;
  }
  __syncthreads();
  float scale = s_scale[lane], shift = s_shift[lane];
  float b1v = b1[lane], b2v = b2[lane];
  int gw = blockIdx.x * 8 + w;        // global warp id, 2048 warps total
  for (int rr = 0; rr < 8; rr += 2){  // row pairs: 2 independent chains
    int rowA = gw*8 + rr, rowB = rowA + 1;
    float hnA = g_hf[(size_t)rowA*HID + lane] * scale + shift;
    float hnB = g_hf[(size_t)rowB*HID + lane] * scale + shift;
    float r1A = b1v, r1B = b1v;
    #pragma unroll
    for (int g = 0; g < HID; g++){
      float wv = sW1[g*HID + lane];
      r1A += __shfl_sync(FULL, hnA, g) * wv;
      r1B += __shfl_sync(FULL, hnB, g) * wv;
    }
    r1A = r1A > 0.f ? r1A : 0.01f*r1A;
    r1B = r1B > 0.f ? r1B : 0.01f*r1B;
    float r2A = b2v, r2B = b2v;
    #pragma unroll
    for (int g = 0; g < HID; g++){
      float wv = sW2[g*HID + lane];
      r2A += __shfl_sync(FULL, r1A, g) * wv;
      r2B += __shfl_sync(FULL, r1B, g) * wv;
    }
    r2A = r2A > 0.f ? r2A : 0.01f*r2A;
    r2B = r2B > 0.f ? r2B : 0.01f*r2B;
    float accA = 0.f, accB = 0.f;
    #pragma unroll
    for (int g = 0; g < HID; g++){
      float wv = (lane < OUTD) ? sW3[g*OUTD + lane] : 0.f;
      accA += __shfl_sync(FULL, r2A, g) * wv;
      accB += __shfl_sync(FULL, r2B, g) * wv;
    }
    if (lane < OUTD){
      float vA = accA + b3[lane];
      float vB = accB + b3[lane];
      if (lane == 0){
        vA = 1.f / (1.f + expf(-vA));
        vB = 1.f / (1.f + expf(-vB));
      }
      out[(size_t)rowA*OUTD + lane] = vA;
      out[(size_t)rowB*OUTD + lane] = vB;
    }
  }
}

// ---------------- launch ----------------------------------------------------
extern "C" void kernel_launch(void* const* d_in, const int* in_sizes, int n_in,
                              void* d_out, int out_size){
  const float* x    = (const float*)d_in[0];
  const float* adj  = (const float*)d_in[1];
  const float* Wd0  = (const float*)d_in[2];
  const float* bd0  = (const float*)d_in[3];
  const float* Wd1  = (const float*)d_in[4];
  const float* bd1  = (const float*)d_in[5];
  const float* Wd2  = (const float*)d_in[6];
  const float* bd2  = (const float*)d_in[7];
  const float* Wu0  = (const float*)d_in[8];
  const float* bu0  = (const float*)d_in[9];
  const float* Wu1  = (const float*)d_in[10];
  const float* bu1  = (const float*)d_in[11];
  const float* p1   = (const float*)d_in[12];
  const float* p2   = (const float*)d_in[13];
  const float* gamma= (const float*)d_in[14];
  const float* beta = (const float*)d_in[15];
  const float* W1   = (const float*)d_in[16];
  const float* b1   = (const float*)d_in[17];
  const float* W2   = (const float*)d_in[18];
  const float* b2   = (const float*)d_in[19];
  const float* W3   = (const float*)d_in[20];
  const float* b3   = (const float*)d_in[21];
  float* out = (float*)d_out;

  k_csr   <<<BB*NN, 256>>>(adj, x, Wd0);
  k_gcn0  <<<(BB*NN)/8, 256>>>(bd0, p1);
  k_top1  <<<BB, 512>>>();
  k_A1    <<<BB*SLABS, 256>>>(Wd1);
  k_gcn1  <<<(BB*K1 + 7)/8, 256>>>(bd1, p2);
  k_top2  <<<BB, 128>>>();
  k_lvl2  <<<BB*K2, 256>>>(Wd2);
  k_up    <<<BB*UPSLABS, 256>>>(bd2, Wu0, bu0);
  k_zu1   <<<(BB*NN*HID)/256, 256>>>(Wu1);
  k_gcnf  <<<(BB*NN)/8, 256>>>(bu1);
  k_bn1   <<<64, 256>>>();
  k_mlp   <<<(BB*NN)/(8*8), 256>>>(gamma, beta, W1, b1, W2, b2, W3, b3, out);
}

// round 14
// speedup vs baseline: 1.2922x; 1.2922x over previous
#include <cuda_runtime.h>
#include <math.h>

#define BB   16
#define NN   1024
#define HID  32
#define K1   205
#define K2   41
#define K1PAD 208
#define MAXD 96
#define OUTD 4
#define FULL 0xffffffffu
#define SLABS 26
#define ROWS_PER_SLAB 8

// ---------------- scratch (device globals; no allocation) ----------------
__device__ float    g_dis0[BB*NN];
__device__ int      g_cnt[BB*NN];
__device__ int      g_csr[BB*NN*MAXD];
__device__ float    g_z0[BB*NN*HID];
__device__ float    g_h0[BB*NN*HID];
__device__ float    g_score1[BB*NN];
__device__ int      g_perm1[BB*K1];
__device__ float    g_vals1[BB*K1];
__device__ int      g_inv1[BB*NN];
__device__ unsigned g_bmT[BB*32*K1PAD];     // transposed: [b][word][k]
__device__ float    g_A1[BB*K1*K1];
__device__ float    g_dis1[BB*K1];
__device__ float    g_z1[BB*K1*HID];
__device__ float    g_h1[BB*K1*HID];
__device__ float    g_score2[BB*K1];
__device__ int      g_perm2[BB*K2];
__device__ float    g_vals2[BB*K2];
__device__ int      g_inv2[BB*K1];
__device__ float    g_A2[BB*K2*K2];
__device__ float    g_dis2[BB*K2];
__device__ float    g_z2[BB*K2*HID];
__device__ float    g_h2[BB*K2*HID];
__device__ float    g_zu0[BB*K1*HID];
__device__ float    g_hu[BB*K1*HID];
__device__ float    g_zu1[BB*NN*HID];
__device__ float    g_hf[BB*NN*HID];
__device__ float    g_part[64*HID];
__device__ float    g_part2[64*HID];

// ---------------- bitonic sort: desc key, asc index on tie ----------------
template<int SIZE, int NT>
__device__ __forceinline__ void bitonic(float* key, int* idx, int t){
  for (int k = 2; k <= SIZE; k <<= 1){
    for (int j = k >> 1; j > 0; j >>= 1){
      __syncthreads();
      for (int i = t; i < SIZE; i += NT){
        int ixj = i ^ j;
        if (ixj > i){
          float ka = key[i], kb = key[ixj];
          int   ia = idx[i], ib = idx[ixj];
          bool aFirst = (ka > kb) || (ka == kb && ia < ib);
          bool up = ((i & k) == 0);
          if (up ? !aFirst : aFirst){
            key[i] = kb; key[ixj] = ka;
            idx[i] = ib; idx[ixj] = ia;
          }
        }
      }
    }
  }
  __syncthreads();
}

// ---------------- K1: CSR build (warp-ballot scan) + dis0 + z0 -------------
__global__ void k_csr(const float* __restrict__ adj, const float* __restrict__ x,
                      const float* __restrict__ Wd0){
  int row = blockIdx.x;               // b*NN + i
  int t   = threadIdx.x;              // 256 threads, 4 cols each (float4)
  int w   = t >> 5, lane = t & 31;
  const float4* arow = (const float4*)(adj + (size_t)row * NN);
  float4 v = arow[t];
  int c0 = v.x != 0.f, c1 = v.y != 0.f, c2 = v.z != 0.f, c3 = v.w != 0.f;
  unsigned m0 = __ballot_sync(FULL, c0);
  unsigned m1 = __ballot_sync(FULL, c1);
  unsigned m2 = __ballot_sync(FULL, c2);
  unsigned m3 = __ballot_sync(FULL, c3);
  int wtotal = __popc(m0) + __popc(m1) + __popc(m2) + __popc(m3);
  __shared__ int swt[8];
  if (lane == 0) swt[w] = wtotal;
  __syncthreads();
  int wbase = 0, total = 0;
  #pragma unroll
  for (int q = 0; q < 8; q++){
    int tv = swt[q];
    if (q < w) wbase += tv;
    total += tv;
  }
  unsigned lt = (1u << lane) - 1u;
  int p0 = wbase + __popc(m0 & lt);
  int p1 = wbase + __popc(m0) + __popc(m1 & lt);
  int p2 = wbase + __popc(m0) + __popc(m1) + __popc(m2 & lt);
  int p3 = wbase + __popc(m0) + __popc(m1) + __popc(m2) + __popc(m3 & lt);
  int* crow = g_csr + (size_t)row * MAXD;
  int jb = t * 4;
  if (c0 && p0 < MAXD) crow[p0] = jb;
  if (c1 && p1 < MAXD) crow[p1] = jb + 1;
  if (c2 && p2 < MAXD) crow[p2] = jb + 2;
  if (c3 && p3 < MAXD) crow[p3] = jb + 3;
  float dis = rsqrtf((float)total + 2.f);      // deg = rowsum + 2, always > 0
  if (t == 0){ g_cnt[row] = total < MAXD ? total : MAXD; g_dis0[row] = dis; }
  if (t < HID){
    const float* xr = x + (size_t)row * 3;
    float z = xr[0]*Wd0[t] + xr[1]*Wd0[HID + t] + xr[2]*Wd0[2*HID + t];
    g_z0[row*HID + t] = dis * z;
  }
}

// ---------------- K2: gcn0 aggregate + relu + score1 ----------------------
__global__ void k_gcn0(const float* __restrict__ bd0, const float* __restrict__ p1){
  int w = (blockIdx.x * blockDim.x + threadIdx.x) >> 5;
  int lane = threadIdx.x & 31;
  if (w >= BB*NN) return;
  int b = w >> 10;
  const float* zb = g_z0 + (size_t)b * NN * HID;
  float a0 = 2.f * g_z0[(size_t)w * HID + lane], a1 = 0.f;
  int cnt = g_cnt[w];
  const int* crow = g_csr + (size_t)w * MAXD;
  int q = 0;
  for (; q + 1 < cnt; q += 2){
    a0 += zb[crow[q]*HID + lane];
    a1 += zb[crow[q+1]*HID + lane];
  }
  if (q < cnt) a0 += zb[crow[q]*HID + lane];
  float h = fmaxf(g_dis0[w]*(a0+a1) + bd0[lane], 0.f);
  g_h0[(size_t)w*HID + lane] = h;
  float pv = p1[lane];
  float s = h * pv, pn = pv * pv;
  #pragma unroll
  for (int o = 16; o > 0; o >>= 1){
    s  += __shfl_xor_sync(FULL, s,  o);
    pn += __shfl_xor_sync(FULL, pn, o);
  }
  if (lane == 0) g_score1[w] = tanhf(s * rsqrtf(pn));
}

// ---------------- K3: top-k level1 + inverse map + transposed bitmaps -----
__global__ void k_top1(){
  int b = blockIdx.x;
  int t = threadIdx.x;                // 512 threads
  __shared__ float skey[NN];
  __shared__ int   sidx[NN];
  for (int i = t; i < NN; i += 512){ skey[i] = g_score1[b*NN + i]; sidx[i] = i; }
  bitonic<NN,512>(skey, sidx, t);
  for (int i = t; i < NN; i += 512) g_inv1[b*NN + i] = -1;
  __syncthreads();
  if (t < K1){
    g_perm1[b*K1 + t] = sidx[t];
    g_vals1[b*K1 + t] = skey[t];
    g_inv1[b*NN + sidx[t]] = t;
  }
  unsigned* bmb = g_bmT + (size_t)b * 32 * K1PAD;
  for (int q = t; q < 32*K1PAD; q += 512) bmb[q] = 0u;
  __syncthreads();
  int wq = t >> 5, lane = t & 31;
  for (int k = wq; k < K1; k += 16){
    int r = sidx[k];
    int rw = b*NN + r;
    int cnt = g_cnt[rw];
    const int* crow = g_csr + (size_t)rw * MAXD;
    for (int q = lane; q < cnt; q += 32){
      int nb = crow[q];
      atomicOr(&bmb[(nb >> 5)*K1PAD + k], 1u << (nb & 31));
    }
    if (lane == 0) atomicOr(&bmb[(r >> 5)*K1PAD + k], 1u << (r & 31));  // +I
  }
}

// ---------------- K4: A1 = augment(adj)[perm1,perm1] + dis1 + z1 ----------
__global__ void k_A1(const float* __restrict__ Wd1){
  int b    = blockIdx.x / SLABS;
  int slab = blockIdx.x % SLABS;
  int t = threadIdx.x;                // 256 threads = 8 warps
  int w = t >> 5, lane = t & 31;
  __shared__ unsigned s_bmT[32*K1PAD];
  const unsigned* bmb = g_bmT + (size_t)b * 32 * K1PAD;
  for (int q = t; q < 32*K1PAD; q += 256) s_bmT[q] = bmb[q];
  __syncthreads();

  int i = slab * ROWS_PER_SLAB + w;
  if (i >= K1) return;
  unsigned bi[32];
  #pragma unroll
  for (int wd = 0; wd < 32; wd++) bi[wd] = s_bmT[wd*K1PAD + i];
  int rowsum = 0;
  float* Arow = g_A1 + (size_t)(b*K1 + i) * K1;
  for (int jb = 0; jb < K1; jb += 32){
    int j = jb + lane;
    int jj = (j < K1) ? j : 0;        // clamp padded lanes (result discarded)
    int c0 = 0, c1 = 0;
    #pragma unroll
    for (int wd = 0; wd < 16; wd++)
      c0 += __popc(bi[wd] & s_bmT[wd*K1PAD + jj]);
    #pragma unroll
    for (int wd = 16; wd < 32; wd++)
      c1 += __popc(bi[wd] & s_bmT[wd*K1PAD + jj]);
    if (j < K1){
      int v = (j == i) ? 0 : (c0 + c1);
      Arow[j] = (float)v;
      rowsum += v;
    }
  }
  #pragma unroll
  for (int o = 16; o > 0; o >>= 1) rowsum += __shfl_xor_sync(FULL, rowsum, o);
  float dis = rsqrtf((float)rowsum + 2.f);
  if (lane == 0) g_dis1[b*K1 + i] = dis;
  int src = g_perm1[b*K1 + i];
  float val = g_vals1[b*K1 + i];
  const float* h0r = g_h0 + (size_t)(b*NN + src) * HID;
  float acc = 0.f;
  #pragma unroll
  for (int g = 0; g < HID; g++) acc += h0r[g]*val * Wd1[g*HID + lane];
  g_z1[(size_t)(b*K1 + i)*HID + lane] = dis * acc;
}

// ---------------- K5: gcn1 (SMEM-staged z1) + relu + score2 ---------------
// grid = BB*SLABS (416 blocks); each block stages z1[b] once, 8 warps x 1 row.
__global__ void k_gcn1(const float* __restrict__ bd1, const float* __restrict__ p2){
  __shared__ float s_z[K1*HID];       // 26.2 KB
  int b = blockIdx.x / SLABS, slab = blockIdx.x % SLABS;
  int t = threadIdx.x, w = t >> 5, lane = t & 31;
  for (int q = t; q < K1*HID; q += 256) s_z[q] = g_z1[(size_t)b*K1*HID + q];
  __syncthreads();
  int i = slab * ROWS_PER_SLAB + w;
  if (i >= K1) return;
  int row = b*K1 + i;
  const float* Ar = g_A1 + (size_t)row * K1;
  float a0 = 2.f * s_z[i*HID + lane], a1 = 0.f, a2 = 0.f, a3 = 0.f;
  int j = 0;
  for (; j + 3 < K1; j += 4){
    a0 += Ar[j]   * s_z[j*HID     + lane];
    a1 += Ar[j+1] * s_z[(j+1)*HID + lane];
    a2 += Ar[j+2] * s_z[(j+2)*HID + lane];
    a3 += Ar[j+3] * s_z[(j+3)*HID + lane];
  }
  for (; j < K1; j++) a0 += Ar[j] * s_z[j*HID + lane];
  float h = fmaxf(g_dis1[row]*((a0+a1)+(a2+a3)) + bd1[lane], 0.f);
  g_h1[(size_t)row*HID + lane] = h;
  float pv = p2[lane];
  float s = h * pv, pn = pv * pv;
  #pragma unroll
  for (int o = 16; o > 0; o >>= 1){
    s  += __shfl_xor_sync(FULL, s,  o);
    pn += __shfl_xor_sync(FULL, pn, o);
  }
  if (lane == 0) g_score2[row] = tanhf(s * rsqrtf(pn));
}

// ---------------- K6: top-k level2 + inverse map ---------------------------
__global__ void k_top2(){
  int b = blockIdx.x, t = threadIdx.x;   // 128 threads
  __shared__ float skey[256];
  __shared__ int   sidx[256];
  for (int i = t; i < 256; i += 128){
    skey[i] = (i < K1) ? g_score2[b*K1 + i] : -2.f;   // scores in [-1,1]
    sidx[i] = i;
  }
  bitonic<256,128>(skey, sidx, t);
  for (int i = t; i < K1; i += 128) g_inv2[b*K1 + i] = -1;
  __syncthreads();
  if (t < K2){
    g_perm2[b*K2 + t] = sidx[t];
    g_vals2[b*K2 + t] = skey[t];
    g_inv2[b*K1 + sidx[t]] = t;
  }
}

// ---------------- K7: A2 = augment(A1)[perm2,perm2] + dis2 + z2 -----------
__global__ void k_lvl2(const float* __restrict__ Wd2){
  int b = blockIdx.x / K2, i = blockIdx.x % K2;
  __shared__ float srow[K1];
  __shared__ float ssum;
  int t = threadIdx.x;                 // 256 threads
  int pi = g_perm2[b*K2 + i];
  if (t == 0) ssum = 0.f;
  for (int q = t; q < K1; q += 256)
    srow[q] = g_A1[(size_t)(b*K1 + pi)*K1 + q] + (q == pi ? 1.f : 0.f);
  __syncthreads();
  float local = 0.f;
  if (t < K2){
    int pj = g_perm2[b*K2 + t];
    const float* Aj = g_A1 + (size_t)(b*K1 + pj)*K1;
    float dot = 0.f;
    for (int q = 0; q < K1; q++) dot += srow[q] * (Aj[q] + (q == pj ? 1.f : 0.f));
    float v = (t == i) ? 0.f : dot;
    g_A2[(size_t)(b*K2 + i)*K2 + t] = v;
    local = v;
  }
  atomicAdd(&ssum, local);             // exact integer sums
  __syncthreads();
  float dis = rsqrtf(ssum + 2.f);
  if (t == 0) g_dis2[b*K2 + i] = dis;
  if (t < HID){
    int src = g_perm2[b*K2 + i];
    float val = g_vals2[b*K2 + i];
    const float* h1r = g_h1 + (size_t)(b*K1 + src) * HID;
    float acc = 0.f;
    #pragma unroll
    for (int g = 0; g < HID; g++) acc += h1r[g]*val * Wd2[g*HID + t];
    g_z2[(size_t)(b*K2 + i)*HID + t] = dis * acc;
  }
}

// ---------------- K8: gcn2 aggregate + relu -> h2 --------------------------
__global__ void k_gcn2(const float* __restrict__ bd2){
  int w = (blockIdx.x * blockDim.x + threadIdx.x) >> 5;
  int lane = threadIdx.x & 31;
  if (w >= BB*K2) return;
  int b = w / K2, i = w - b*K2;
  const float* z  = g_z2 + (size_t)b * K2 * HID;
  const float* Ar = g_A2 + (size_t)w * K2;
  float acc = 2.f * z[i*HID + lane];
  for (int j = 0; j < K2; j++) acc += Ar[j] * z[j*HID + lane];
  g_h2[(size_t)w*HID + lane] = fmaxf(g_dis2[w]*acc + bd2[lane], 0.f);
}

// ---------------- K9: zu0 = dis1 * ((h1 + scatter(h2)) @ Wu0) --------------
__global__ void k_zu0(const float* __restrict__ Wu0){
  int idx = blockIdx.x * blockDim.x + threadIdx.x;
  if (idx >= BB*K1*HID) return;
  int f = idx & 31;
  int rk = idx >> 5;                   // b*K1 + k
  int b = rk / K1;
  int iv = g_inv2[rk];
  const float* h1r = g_h1 + (size_t)rk * HID;
  const float* h2r = g_h2 + (size_t)(b*K2 + (iv < 0 ? 0 : iv)) * HID;
  float acc = 0.f;
  #pragma unroll
  for (int g = 0; g < HID; g++){
    float us = h1r[g] + (iv >= 0 ? h2r[g] : 0.f);
    acc += us * Wu0[g*HID + f];
  }
  g_zu0[idx] = g_dis1[rk] * acc;
}

// ---------------- K10: gcn up0 (SMEM-staged zu0) + relu -> hu --------------
// grid = BB*SLABS (416 blocks); each block stages zu0[b] once, 8 warps x 1 row.
__global__ void k_gcnu0(const float* __restrict__ bu0){
  __shared__ float s_z[K1*HID];       // 26.2 KB
  int b = blockIdx.x / SLABS, slab = blockIdx.x % SLABS;
  int t = threadIdx.x, w = t >> 5, lane = t & 31;
  for (int q = t; q < K1*HID; q += 256) s_z[q] = g_zu0[(size_t)b*K1*HID + q];
  __syncthreads();
  int i = slab * ROWS_PER_SLAB + w;
  if (i >= K1) return;
  int row = b*K1 + i;
  const float* Ar = g_A1 + (size_t)row * K1;
  float a0 = 2.f * s_z[i*HID + lane], a1 = 0.f, a2 = 0.f, a3 = 0.f;
  int j = 0;
  for (; j + 3 < K1; j += 4){
    a0 += Ar[j]   * s_z[j*HID     + lane];
    a1 += Ar[j+1] * s_z[(j+1)*HID + lane];
    a2 += Ar[j+2] * s_z[(j+2)*HID + lane];
    a3 += Ar[j+3] * s_z[(j+3)*HID + lane];
  }
  for (; j < K1; j++) a0 += Ar[j] * s_z[j*HID + lane];
  g_hu[(size_t)row*HID + lane] = fmaxf(g_dis1[row]*((a0+a1)+(a2+a3)) + bu0[lane], 0.f);
}

// ---------------- K11: zu1 = dis0 * ((h0 + scatter(hu)) @ Wu1) -------------
__global__ void k_zu1(const float* __restrict__ Wu1){
  int idx = blockIdx.x * blockDim.x + threadIdx.x;   // < BB*NN*HID
  int f = idx & 31;
  int rn = idx >> 5;                   // b*NN + n
  int b = rn >> 10;
  int iv = g_inv1[rn];
  const float* h0r = g_h0 + (size_t)rn * HID;
  const float* hur = g_hu + (size_t)(b*K1 + (iv < 0 ? 0 : iv)) * HID;
  float acc = 0.f;
  #pragma unroll
  for (int g = 0; g < HID; g++){
    float us = h0r[g] + (iv >= 0 ? hur[g] : 0.f);
    acc += us * Wu1[g*HID + f];
  }
  g_zu1[idx] = g_dis0[rn] * acc;
}

// ---------------- K12: final gcn via CSR (no relu) -> hf -------------------
__global__ void k_gcnf(const float* __restrict__ bu1){
  int w = (blockIdx.x * blockDim.x + threadIdx.x) >> 5;
  int lane = threadIdx.x & 31;
  if (w >= BB*NN) return;
  int b = w >> 10;
  const float* zb = g_zu1 + (size_t)b * NN * HID;
  float a0 = 2.f * g_zu1[(size_t)w*HID + lane], a1 = 0.f;
  int cnt = g_cnt[w];
  const int* crow = g_csr + (size_t)w * MAXD;
  int q = 0;
  for (; q + 1 < cnt; q += 2){
    a0 += zb[crow[q]*HID + lane];
    a1 += zb[crow[q+1]*HID + lane];
  }
  if (q < cnt) a0 += zb[crow[q]*HID + lane];
  g_hf[(size_t)w*HID + lane] = g_dis0[w]*(a0+a1) + bu1[lane];
}

// ---------------- K13: batch-norm stats stage 1 ----------------------------
__global__ void k_bn1(){
  int blk = blockIdx.x;                // 64 blocks
  int t = threadIdx.x;
  int w = t >> 5, lane = t & 31;
  float s = 0.f, s2 = 0.f;
  int rowbase = blk * 256;
  for (int r = w; r < 256; r += 8){
    float v = g_hf[(size_t)(rowbase + r)*HID + lane];
    s += v; s2 += v*v;
  }
  __shared__ float sh[8][32], sh2[8][32];
  sh[w][lane] = s; sh2[w][lane] = s2;
  __syncthreads();
  if (w == 0){
    float a = 0.f, a2 = 0.f;
    #pragma unroll
    for (int q = 0; q < 8; q++){ a += sh[q][lane]; a2 += sh2[q][lane]; }
    g_part[blk*HID + lane]  = a;
    g_part2[blk*HID + lane] = a2;
  }
}

// ---------------- K14: fused BN-finalize + BN-apply + MLP + sigmoid --------
__global__ void k_mlp(const float* __restrict__ gamma, const float* __restrict__ beta,
                      const float* __restrict__ W1, const float* __restrict__ b1,
                      const float* __restrict__ W2, const float* __restrict__ b2,
                      const float* __restrict__ W3, const float* __restrict__ b3,
                      float* __restrict__ out){
  int t = threadIdx.x;                // 256 threads = 8 warps
  int w = t >> 5, lane = t & 31;
  __shared__ float sp[8][32], sp2[8][32];
  __shared__ float s_scale[32], s_shift[32];
  __shared__ float sW1[HID*HID], sW2[HID*HID], sW3[HID*OUTD];
  for (int q = t; q < HID*HID; q += 256){ sW1[q] = W1[q]; sW2[q] = W2[q]; }
  if (t < HID*OUTD) sW3[t] = W3[t];
  float ps = 0.f, ps2 = 0.f;
  for (int q = w*8; q < w*8 + 8; q++){
    ps  += g_part[q*HID + lane];
    ps2 += g_part2[q*HID + lane];
  }
  sp[w][lane] = ps; sp2[w][lane] = ps2;
  __syncthreads();
  if (w == 0){
    float s = 0.f, s2 = 0.f;
    #pragma unroll
    for (int q = 0; q < 8; q++){ s += sp[q][lane]; s2 += sp2[q][lane]; }
    const float inv = 1.f / (float)(BB*NN);
    float mean = s * inv;
    float var  = s2 * inv - mean*mean;
    float sc = gamma[lane] * rsqrtf(var + 1e-5f);
    s_scale[lane] = sc;
    s_shift[lane] = beta[lane] - mean*sc;
  }
  __syncthreads();
  float scale = s_scale[lane], shift = s_shift[lane];
  float b1v = b1[lane], b2v = b2[lane];
  int gw = blockIdx.x * 8 + w;        // global warp id, 2048 warps total
  for (int rr = 0; rr < 8; rr += 2){  // row pairs: 2 independent chains
    int rowA = gw*8 + rr, rowB = rowA + 1;
    float hnA = g_hf[(size_t)rowA*HID + lane] * scale + shift;
    float hnB = g_hf[(size_t)rowB*HID + lane] * scale + shift;
    float r1A = b1v, r1B = b1v;
    #pragma unroll
    for (int g = 0; g < HID; g++){
      float wv = sW1[g*HID + lane];
      r1A += __shfl_sync(FULL, hnA, g) * wv;
      r1B += __shfl_sync(FULL, hnB, g) * wv;
    }
    r1A = r1A > 0.f ? r1A : 0.01f*r1A;
    r1B = r1B > 0.f ? r1B : 0.01f*r1B;
    float r2A = b2v, r2B = b2v;
    #pragma unroll
    for (int g = 0; g < HID; g++){
      float wv = sW2[g*HID + lane];
      r2A += __shfl_sync(FULL, r1A, g) * wv;
      r2B += __shfl_sync(FULL, r1B, g) * wv;
    }
    r2A = r2A > 0.f ? r2A : 0.01f*r2A;
    r2B = r2B > 0.f ? r2B : 0.01f*r2B;
    float accA = 0.f, accB = 0.f;
    #pragma unroll
    for (int g = 0; g < HID; g++){
      float wv = (lane < OUTD) ? sW3[g*OUTD + lane] : 0.f;
      accA += __shfl_sync(FULL, r2A, g) * wv;
      accB += __shfl_sync(FULL, r2B, g) * wv;
    }
    if (lane < OUTD){
      float vA = accA + b3[lane];
      float vB = accB + b3[lane];
      if (lane == 0){
        vA = 1.f / (1.f + expf(-vA));
        vB = 1.f / (1.f + expf(-vB));
      }
      out[(size_t)rowA*OUTD + lane] = vA;
      out[(size_t)rowB*OUTD + lane] = vB;
    }
  }
}

// ---------------- launch ----------------------------------------------------
extern "C" void kernel_launch(void* const* d_in, const int* in_sizes, int n_in,
                              void* d_out, int out_size){
  const float* x    = (const float*)d_in[0];
  const float* adj  = (const float*)d_in[1];
  const float* Wd0  = (const float*)d_in[2];
  const float* bd0  = (const float*)d_in[3];
  const float* Wd1  = (const float*)d_in[4];
  const float* bd1  = (const float*)d_in[5];
  const float* Wd2  = (const float*)d_in[6];
  const float* bd2  = (const float*)d_in[7];
  const float* Wu0  = (const float*)d_in[8];
  const float* bu0  = (const float*)d_in[9];
  const float* Wu1  = (const float*)d_in[10];
  const float* bu1  = (const float*)d_in[11];
  const float* p1   = (const float*)d_in[12];
  const float* p2   = (const float*)d_in[13];
  const float* gamma= (const float*)d_in[14];
  const float* beta = (const float*)d_in[15];
  const float* W1   = (const float*)d_in[16];
  const float* b1   = (const float*)d_in[17];
  const float* W2   = (const float*)d_in[18];
  const float* b2   = (const float*)d_in[19];
  const float* W3   = (const float*)d_in[20];
  const float* b3   = (const float*)d_in[21];
  float* out = (float*)d_out;

  k_csr   <<<BB*NN, 256>>>(adj, x, Wd0);
  k_gcn0  <<<(BB*NN)/8, 256>>>(bd0, p1);
  k_top1  <<<BB, 512>>>();
  k_A1    <<<BB*SLABS, 256>>>(Wd1);
  k_gcn1  <<<BB*SLABS, 256>>>(bd1, p2);
  k_top2  <<<BB, 128>>>();
  k_lvl2  <<<BB*K2, 256>>>(Wd2);
  k_gcn2  <<<(BB*K2 + 7)/8, 256>>>(bd2);
  k_zu0   <<<(BB*K1*HID + 255)/256, 256>>>(Wu0);
  k_gcnu0 <<<BB*SLABS, 256>>>(bu0);
  k_zu1   <<<(BB*NN*HID)/256, 256>>>(Wu1);
  k_gcnf  <<<(BB*NN)/8, 256>>>(bu1);
  k_bn1   <<<64, 256>>>();
  k_mlp   <<<(BB*NN)/(8*8), 256>>>(gamma, beta, W1, b1, W2, b2, W3, b3, out);
}